// round 7
// baseline (speedup 1.0000x reference)
#include <cuda_runtime.h>
#include <cuda_fp16.h>
#include <cstdint>

// ---------------- static scratch (no allocations allowed) ----------------
#define MAXN 100000
#define MAXE 3200000
#define MAXG 256

__device__ __half g_h16T[(size_t)MAXN * 128];  // gathered GEMM outputs (fp16)
__device__ __half g_h16X[(size_t)MAXN * 64];   // SG chain ping
__device__ __half g_h16Y[(size_t)MAXN * 64];   // SG chain pong
__device__ float  g_bufA[(size_t)MAXN * 128];  // prop outputs (fp32, read linearly)
__device__ float  g_bufB[(size_t)MAXN * 64];   // SG linear out (fp32, pooled)
__device__ float  g_deg[MAXN];
__device__ float  g_dinv[MAXN];
__device__ int    g_rowptr[MAXN + 1];
__device__ int    g_tmp[MAXN];
__device__ int    g_sums[256];
__device__ int    g_fill[MAXN];
__device__ int2   g_pairs[MAXE];  // (src, norm-as-int)
__device__ int    g_start[MAXG + 1];
__device__ float  g_pooled[MAXG * 64];

static inline int cdiv(long long a, int b) { return (int)((a + b - 1) / b); }

// ---------------- degree / norm prep ----------------
__global__ void deg_init_kernel(float* __restrict__ deg, int* __restrict__ fill, int N) {
    int i = blockIdx.x * blockDim.x + threadIdx.x;
    if (i < N) { deg[i] = 1.0f; fill[i] = 0; }  // self loop
}

__global__ void deg_accum_kernel(const int* __restrict__ dst, float* __restrict__ deg, int E) {
    int e = blockIdx.x * blockDim.x + threadIdx.x;
    if (e < E) atomicAdd(&deg[dst[e]], 1.0f);
}

__global__ void dinv_kernel(const float* __restrict__ deg, float* __restrict__ dinv, int N) {
    int i = blockIdx.x * blockDim.x + threadIdx.x;
    if (i < N) dinv[i] = rsqrtf(deg[i]);
}

// ---------------- CSR build: scan of in-degree (excl self loops) ----------------
__global__ void scan_chunk_kernel(const float* __restrict__ deg, int* __restrict__ excl,
                                  int* __restrict__ sums, int N) {
    __shared__ int sh[1024];
    int i = blockIdx.x * 1024 + threadIdx.x;
    int v = 0;
    if (i < N) v = (int)deg[i] - 1;
    sh[threadIdx.x] = v;
    __syncthreads();
    for (int off = 1; off < 1024; off <<= 1) {
        int add = (threadIdx.x >= off) ? sh[threadIdx.x - off] : 0;
        __syncthreads();
        sh[threadIdx.x] += add;
        __syncthreads();
    }
    if (i < N) excl[i] = sh[threadIdx.x] - v;
    if (threadIdx.x == 1023) sums[blockIdx.x] = sh[1023];
}

__global__ void scan_sums_kernel(int* __restrict__ sums, int nchunks) {
    if (threadIdx.x == 0 && blockIdx.x == 0) {
        int run = 0;
        for (int c = 0; c < nchunks; c++) {
            int v = sums[c];
            sums[c] = run;
            run += v;
        }
    }
}

__global__ void finalize_rowptr_kernel(const int* __restrict__ excl, const int* __restrict__ sums,
                                       int* __restrict__ rp, int N, int E) {
    int i = blockIdx.x * blockDim.x + threadIdx.x;
    if (i < N) rp[i] = excl[i] + sums[i >> 10];
    if (i == 0) rp[N] = E;
}

__global__ void scatter_kernel(const int* __restrict__ src, const int* __restrict__ dst,
                               const float* __restrict__ dinv, const int* __restrict__ rp,
                               int* __restrict__ fill, int2* __restrict__ pairs, int E) {
    int e = blockIdx.x * blockDim.x + threadIdx.x;
    if (e >= E) return;
    int s = src[e];
    int d = dst[e];
    int pos = rp[d] + atomicAdd(&fill[d], 1);
    pairs[pos] = make_int2(s, __float_as_int(dinv[s] * dinv[d]));
}

// ---------------- GEMM: OUT[N,DOUT] = act(A)[N,DIN] @ W[DIN,DOUT], fp32 math ----------------
template <int DIN, int DOUT, bool RELU_IN, bool OUT_HALF>
__global__ void gemm_kernel(const float* __restrict__ A, const float* __restrict__ W,
                            void* __restrict__ outv, int N) {
    constexpr int TR = 32;
    constexpr int KC = 32;
    constexpr int CT = DOUT / 32;  // 4 or 2
    __shared__ float As[TR][KC + 1];
    __shared__ float Ws[KC][DOUT];
    const int tid = threadIdx.x;  // 128
    const int tx = tid & 31;
    const int ty = tid >> 5;
    const int rbase = blockIdx.x * TR;

    float acc[8][CT];
#pragma unroll
    for (int i = 0; i < 8; i++)
#pragma unroll
        for (int j = 0; j < CT; j++) acc[i][j] = 0.f;

    for (int k0 = 0; k0 < DIN; k0 += KC) {
#pragma unroll
        for (int it = 0; it < 2; it++) {
            int r = (tid >> 3) + it * 16;
            int c = (tid & 7) * 4;
            float4 v = make_float4(0.f, 0.f, 0.f, 0.f);
            int gr = rbase + r;
            if (gr < N) v = *(const float4*)(A + (size_t)gr * DIN + k0 + c);
            if (RELU_IN) {
                v.x = fmaxf(v.x, 0.f); v.y = fmaxf(v.y, 0.f);
                v.z = fmaxf(v.z, 0.f); v.w = fmaxf(v.w, 0.f);
            }
            As[r][c + 0] = v.x; As[r][c + 1] = v.y;
            As[r][c + 2] = v.z; As[r][c + 3] = v.w;
        }
        constexpr int WLOOP = (KC * DOUT) / (128 * 4);
#pragma unroll
        for (int it = 0; it < WLOOP; it++) {
            int idx = (it * 128 + tid) * 4;
            int kk = idx / DOUT;
            int c = idx % DOUT;
            *(float4*)(&Ws[kk][c]) = *(const float4*)(W + (size_t)(k0 + kk) * DOUT + c);
        }
        __syncthreads();
#pragma unroll
        for (int kk = 0; kk < KC; kk++) {
            float wv[CT];
#pragma unroll
            for (int j = 0; j < CT; j++) wv[j] = Ws[kk][tx * CT + j];
#pragma unroll
            for (int rr = 0; rr < 8; rr++) {
                float a = As[ty * 8 + rr][kk];
#pragma unroll
                for (int j = 0; j < CT; j++) acc[rr][j] = fmaf(a, wv[j], acc[rr][j]);
            }
        }
        __syncthreads();
    }
#pragma unroll
    for (int rr = 0; rr < 8; rr++) {
        int gr = rbase + ty * 8 + rr;
        if (gr >= N) continue;
        if constexpr (OUT_HALF) {
            __half* out = (__half*)outv;
            __half2* p = (__half2*)(out + (size_t)gr * DOUT + tx * CT);
#pragma unroll
            for (int j = 0; j < CT / 2; j++)
                p[j] = __floats2half2_rn(acc[rr][2 * j], acc[rr][2 * j + 1]);
        } else {
            float* out = (float*)outv;
            if constexpr (CT == 4) {
                *(float4*)(out + (size_t)gr * DOUT + tx * 4) =
                    make_float4(acc[rr][0], acc[rr][1], acc[rr][2], acc[rr][3]);
            } else {
                *(float2*)(out + (size_t)gr * DOUT + tx * 2) =
                    make_float2(acc[rr][0], acc[rr][1]);
            }
        }
    }
}

// ---------------- CSR propagate: half-warp per node, fp16 gather / fp32 accumulate ----------
// out[i] = dinv[i]^2 * act(t[i]) + bias + sum_j norm_j * act(t[src_j])
// Two nodes per warp: lanes 0-15 -> node 2w, lanes 16-31 -> node 2w+1.
// Each lane loads D/16 halves (uint2 for D=64, uint4 for D=128) -> one LDG
// instruction gathers BOTH nodes' rows. Pairs loads are uniform-per-half.
template <int D, bool RELU, bool OUT_HALF>
__global__ void csr_prop16_kernel(const __half* __restrict__ t, void* __restrict__ outv,
                                  const int2* __restrict__ pairs, const int* __restrict__ rp,
                                  const float* __restrict__ dinv, const float* __restrict__ bias,
                                  int N, int E) {
    constexpr int F = D / 16;  // floats per lane: 4 (D=64) or 8 (D=128)
    int gwarp = (blockIdx.x * blockDim.x + threadIdx.x) >> 5;
    int lane = threadIdx.x & 31;
    int half = lane >> 4;
    int hl = lane & 15;
    int i = gwarp * 2 + half;
    bool valid = (i < N);
    int ic = valid ? i : (N - 1);
    int j0 = rp[ic];
    int cnt = valid ? (rp[ic + 1] - j0) : 0;
    int maxcnt = max(cnt, __shfl_xor_sync(0xFFFFFFFFu, cnt, 16));
    int jcap = max(cnt - 1, 0);

    float acc[F];
#pragma unroll
    for (int v = 0; v < F; v++) acc[v] = 0.f;

    auto load_row = [&](int s, float* f) {
        if constexpr (F == 4) {
            uint2 u = *((const uint2*)(t + (size_t)s * D) + hl);
            float2 fa = __half22float2(*(__half2*)&u.x);
            float2 fb = __half22float2(*(__half2*)&u.y);
            f[0] = fa.x; f[1] = fa.y; f[2] = fb.x; f[3] = fb.y;
        } else {
            uint4 u = *((const uint4*)(t + (size_t)s * D) + hl);
            float2 fa = __half22float2(*(__half2*)&u.x);
            float2 fb = __half22float2(*(__half2*)&u.y);
            float2 fc = __half22float2(*(__half2*)&u.z);
            float2 fd = __half22float2(*(__half2*)&u.w);
            f[0] = fa.x; f[1] = fa.y; f[2] = fb.x; f[3] = fb.y;
            f[4] = fc.x; f[5] = fc.y; f[6] = fd.x; f[7] = fd.y;
        }
    };

    for (int k = 0; k < maxcnt; k += 4) {
        int2 p[4];
        float a[4][F];
#pragma unroll
        for (int u = 0; u < 4; u++) {
            int kk = min(k + u, jcap);
            int jj = min(j0 + kk, E - 1);
            p[u] = pairs[jj];
            if (k + u >= cnt) p[u].y = 0;  // zero weight for exhausted half
        }
#pragma unroll
        for (int u = 0; u < 4; u++) load_row(p[u].x, a[u]);
#pragma unroll
        for (int u = 0; u < 4; u++) {
            float w = __int_as_float(p[u].y);
#pragma unroll
            for (int v = 0; v < F; v++) {
                float xv = RELU ? fmaxf(a[u][v], 0.f) : a[u][v];
                acc[v] = fmaf(w, xv, acc[v]);
            }
        }
    }

    if (!valid) return;

    float dv = dinv[i];
    float sc = dv * dv;
    float self[F];
    load_row(i, self);
    float o[F];
#pragma unroll
    for (int v = 0; v < F; v++) {
        float sv = RELU ? fmaxf(self[v], 0.f) : self[v];
        float b = bias ? bias[hl * F + v] : 0.f;
        o[v] = fmaf(sc, sv, acc[v]) + b;
    }

    if constexpr (OUT_HALF) {
        __half* out = (__half*)outv;
        if constexpr (F == 4) {
            __half2 ha = __floats2half2_rn(o[0], o[1]);
            __half2 hb = __floats2half2_rn(o[2], o[3]);
            uint2 u;
            u.x = *(unsigned*)&ha; u.y = *(unsigned*)&hb;
            *((uint2*)(out + (size_t)i * D) + hl) = u;
        } else {
            __half2 ha = __floats2half2_rn(o[0], o[1]);
            __half2 hb = __floats2half2_rn(o[2], o[3]);
            __half2 hc = __floats2half2_rn(o[4], o[5]);
            __half2 hd = __floats2half2_rn(o[6], o[7]);
            uint4 u;
            u.x = *(unsigned*)&ha; u.y = *(unsigned*)&hb;
            u.z = *(unsigned*)&hc; u.w = *(unsigned*)&hd;
            *((uint4*)(out + (size_t)i * D) + hl) = u;
        }
    } else {
        float* out = (float*)outv;
        if constexpr (F == 4) {
            *((float4*)(out + (size_t)i * D) + hl) = make_float4(o[0], o[1], o[2], o[3]);
        } else {
            *((float4*)(out + (size_t)i * D) + hl * 2) = make_float4(o[0], o[1], o[2], o[3]);
            *((float4*)(out + (size_t)i * D) + hl * 2 + 1) = make_float4(o[4], o[5], o[6], o[7]);
        }
    }
}

// ---------------- segment starts via binary search on sorted batch (int32) ----------------
__global__ void seg_start_kernel(const int* __restrict__ batch, int N, int G,
                                 int* __restrict__ start) {
    int g = blockIdx.x * blockDim.x + threadIdx.x;
    if (g > G) return;
    int lo = 0, hi = N;
    while (lo < hi) {
        int mid = (lo + hi) >> 1;
        if (batch[mid] < g) lo = mid + 1; else hi = mid;
    }
    start[g] = lo;
}

// ---------------- max pool per graph (+ sg_b folded in); 4 row-groups ----------------
__global__ void pool_kernel(const float* __restrict__ z, const int* __restrict__ start,
                            const float* __restrict__ sgb, float* __restrict__ pooled) {
    int g = blockIdx.x;
    int tx = threadIdx.x & 63;
    int ty = threadIdx.x >> 6;  // 0..3
    int s = start[g], e = start[g + 1];
    float m = -3.4028235e38f;
    for (int i = s + ty; i < e; i += 4) m = fmaxf(m, z[(size_t)i * 64 + tx]);
    __shared__ float sm[4][64];
    sm[ty][tx] = m;
    __syncthreads();
    if (ty == 0) {
        m = fmaxf(fmaxf(sm[0][tx], sm[1][tx]), fmaxf(sm[2][tx], sm[3][tx]));
        pooled[g * 64 + tx] = m + sgb[tx];
    }
}

// ---------------- head MLP ----------------
__global__ void head_kernel(const float* __restrict__ pooled,
                            const float* __restrict__ fc1w, const float* __restrict__ fc1b,
                            const float* __restrict__ fc2w, const float* __restrict__ fc2b,
                            const float* __restrict__ cpdw, const float* __restrict__ cpdb,
                            const float* __restrict__ combw, const float* __restrict__ combb,
                            float* __restrict__ out, int G) {
    int g = blockIdx.x;
    int t = threadIdx.x;  // 64
    __shared__ float z0[64], z1[32], z2[16];
    z0[t] = pooled[g * 64 + t];
    __syncthreads();
    if (t < 32) {
        float s = fc1b[t];
        for (int k = 0; k < 64; k++) s = fmaf(z0[k], fc1w[k * 32 + t], s);
        z1[t] = fmaxf(s, 0.f);
    }
    __syncthreads();
    if (t < 16) {
        float s = fc2b[t];
        for (int k = 0; k < 32; k++) s = fmaf(z1[k], fc2w[k * 16 + t], s);
        z2[t] = fmaxf(s, 0.f);
    }
    __syncthreads();
    if (t == 0) {
        float s = cpdb[0];
        for (int k = 0; k < 16; k++) s = fmaf(z2[k], cpdw[k], s);
        out[g] = s;
    }
    if (t == 1) {
        float s = combb[0];
        for (int k = 0; k < 16; k++) s = fmaf(z2[k], combw[k], s);
        out[G + g] = s;
    }
}

// ---------------- host side ----------------
extern "C" void kernel_launch(void* const* d_in, const int* in_sizes, int n_in,
                              void* d_out, int out_size) {
    const float* x     = (const float*)d_in[0];
    const int*   ei    = (const int*)d_in[1];
    const int*   batch = (const int*)d_in[2];
    const float* enc_w1 = (const float*)d_in[3];
    const float* enc_b1 = (const float*)d_in[4];
    const float* enc_w2 = (const float*)d_in[5];
    const float* enc_b2 = (const float*)d_in[6];
    const float* w1 = (const float*)d_in[7];
    const float* b1 = (const float*)d_in[8];
    const float* w2 = (const float*)d_in[9];
    const float* b2 = (const float*)d_in[10];
    const float* w3 = (const float*)d_in[11];
    const float* b3 = (const float*)d_in[12];
    const float* sg_w = (const float*)d_in[13];
    const float* sg_b = (const float*)d_in[14];
    const float* fc1_w = (const float*)d_in[15];
    const float* fc1_b = (const float*)d_in[16];
    const float* fc2_w = (const float*)d_in[17];
    const float* fc2_b = (const float*)d_in[18];
    const float* cpd_w = (const float*)d_in[19];
    const float* cpd_b = (const float*)d_in[20];
    const float* comb_w = (const float*)d_in[21];
    const float* comb_b = (const float*)d_in[22];
    float* out = (float*)d_out;

    const int N = in_sizes[0] / 128;
    const int E = in_sizes[1] / 2;
    const int G = out_size / 2;

    const int* src = ei;
    const int* dst = ei + E;

    void *pT16, *pX16, *pY16, *pA, *pB, *pDeg, *pDinv, *pRp, *pTmp, *pSums, *pFill,
         *pPairs, *pStart, *pPool;
    cudaGetSymbolAddress(&pT16, g_h16T);
    cudaGetSymbolAddress(&pX16, g_h16X);
    cudaGetSymbolAddress(&pY16, g_h16Y);
    cudaGetSymbolAddress(&pA, g_bufA);
    cudaGetSymbolAddress(&pB, g_bufB);
    cudaGetSymbolAddress(&pDeg, g_deg);
    cudaGetSymbolAddress(&pDinv, g_dinv);
    cudaGetSymbolAddress(&pRp, g_rowptr);
    cudaGetSymbolAddress(&pTmp, g_tmp);
    cudaGetSymbolAddress(&pSums, g_sums);
    cudaGetSymbolAddress(&pFill, g_fill);
    cudaGetSymbolAddress(&pPairs, g_pairs);
    cudaGetSymbolAddress(&pStart, g_start);
    cudaGetSymbolAddress(&pPool, g_pooled);
    __half* T16 = (__half*)pT16;
    __half* X16 = (__half*)pX16;
    __half* Y16 = (__half*)pY16;
    float* bufA = (float*)pA;
    float* bufB = (float*)pB;
    float* deg = (float*)pDeg;
    float* dinv = (float*)pDinv;
    int* rp = (int*)pRp;
    int* tmp = (int*)pTmp;
    int* sums = (int*)pSums;
    int* fill = (int*)pFill;
    int2* pairs = (int2*)pPairs;
    int* start = (int*)pStart;
    float* pooled = (float*)pPool;

    const int TB = 256;
    const int nchunks = cdiv(N, 1024);

    // ---- degree / dinv ----
    deg_init_kernel<<<cdiv(N, TB), TB>>>(deg, fill, N);
    deg_accum_kernel<<<cdiv(E, TB), TB>>>(dst, deg, E);
    dinv_kernel<<<cdiv(N, TB), TB>>>(deg, dinv, N);

    // ---- CSR build (counting sort by dst) ----
    scan_chunk_kernel<<<nchunks, 1024>>>(deg, tmp, sums, N);
    scan_sums_kernel<<<1, 32>>>(sums, nchunks);
    finalize_rowptr_kernel<<<cdiv(N, TB), TB>>>(tmp, sums, rp, N, E);
    scatter_kernel<<<cdiv(E, TB), TB>>>(src, dst, dinv, rp, fill, pairs, E);

    const int gemmB = 128;
    const int gemmGrid = cdiv(N, 32);
    const int propGrid = cdiv(N, 16);  // 2 nodes/warp, 8 warps/block

    // ---- encoder layer 1 ----
    gemm_kernel<128, 128, false, true><<<gemmGrid, gemmB>>>(x, enc_w1, T16, N);
    csr_prop16_kernel<128, false, false><<<propGrid, TB>>>(T16, bufA, pairs, rp, dinv, enc_b1, N, E);

    // ---- encoder layer 2 (relu fused into GEMM A-load) ----
    gemm_kernel<128, 64, true, true><<<gemmGrid, gemmB>>>(bufA, enc_w2, T16, N);
    csr_prop16_kernel<64, false, false><<<propGrid, TB>>>(T16, bufA, pairs, rp, dinv, enc_b2, N, E);

    // ---- conv1 (enc2 output NOT relu'd) ----
    gemm_kernel<64, 64, false, true><<<gemmGrid, gemmB>>>(bufA, w1, T16, N);
    csr_prop16_kernel<64, false, false><<<propGrid, TB>>>(T16, bufA, pairs, rp, dinv, b1, N, E);

    // ---- conv2 ----
    gemm_kernel<64, 64, true, true><<<gemmGrid, gemmB>>>(bufA, w2, T16, N);
    csr_prop16_kernel<64, false, false><<<propGrid, TB>>>(T16, bufA, pairs, rp, dinv, b2, N, E);

    // ---- conv3 (prop writes fp16, pre-relu; relu fused into SG prop1) ----
    gemm_kernel<64, 64, true, true><<<gemmGrid, gemmB>>>(bufA, w3, T16, N);
    csr_prop16_kernel<64, false, true><<<propGrid, TB>>>(T16, X16, pairs, rp, dinv, b3, N, E);

    // ---- SGConv: 4 propagations (all fp16 gather) ----
    csr_prop16_kernel<64, true, true><<<propGrid, TB>>>(X16, Y16, pairs, rp, dinv, nullptr, N, E);
    csr_prop16_kernel<64, false, true><<<propGrid, TB>>>(Y16, X16, pairs, rp, dinv, nullptr, N, E);
    csr_prop16_kernel<64, false, true><<<propGrid, TB>>>(X16, Y16, pairs, rp, dinv, nullptr, N, E);
    csr_prop16_kernel<64, false, false><<<propGrid, TB>>>(Y16, bufA, pairs, rp, dinv, nullptr, N, E);

    // ---- SG linear (bias folded past max-pool) ----
    gemm_kernel<64, 64, false, false><<<gemmGrid, gemmB>>>(bufA, sg_w, bufB, N);

    // ---- pool + head ----
    seg_start_kernel<<<cdiv(G + 1, TB), TB>>>(batch, N, G, start);
    pool_kernel<<<G, 256>>>(bufB, start, sg_b, pooled);
    head_kernel<<<G, 64>>>(pooled, fc1_w, fc1_b, fc2_w, fc2_b,
                           cpd_w, cpd_b, comb_w, comb_b, out, G);
}